// round 6
// baseline (speedup 1.0000x reference)
#include <cuda_runtime.h>
#include <cstdint>

#define BATCH 32
#define NN    512
#define FIN   256
#define FOUT  256
#define EE    2

#define BK      32
#define LDN     36                         // padded stride: normal K-major tiles (floats)
#define LDT1    136                        // padded stride: transposed W tile (k1), 136%32==8
#define LDT2    264                        // padded stride: transposed W2 tile (k2), 264%32==8

#define NT      512                        // threads per CTA (16 warps)

// per-stage float counts
#define K1_AF   (32 * LDT1)                // 4352
#define K1_BF   (256 * LDN)                // 9216
#define K1_STAGE (K1_AF + K1_BF)           // 13568 floats
#define K2_AF   (128 * LDN)                // 4608
#define K2_BF   (256 * LDN)                // 9216  (>= 32*LDT2 = 8448)
#define K2_STAGE (K2_AF + K2_BF)           // 13824 floats

#define NSTAGE  3
#define K1_SMEM (NSTAGE * K1_STAGE * 4)    // 162816 B
#define K2_SMEM (NSTAGE * K2_STAGE * 4)    // 165888 B

// scratch (no allocation allowed): hT[b][e][o][n], tf32-pre-rounded
__device__ float g_hT[(size_t)BATCH * EE * FOUT * NN];

// ---------------------------------------------------------------- helpers ---
__device__ __forceinline__ uint32_t smem_u32(const void* p) {
    uint32_t a;
    asm("{ .reg .u64 t; cvta.to.shared.u64 t, %1; cvt.u32.u64 %0, t; }" : "=r"(a) : "l"(p));
    return a;
}
__device__ __forceinline__ uint32_t to_tf32(float x) {
    uint32_t u;
    asm("cvt.rna.tf32.f32 %0, %1;" : "=r"(u) : "f"(x));
    return u;
}
__device__ __forceinline__ float round_tf32(float x) { return __uint_as_float(to_tf32(x)); }

__device__ __forceinline__ void mma_tf32(float* d,
    uint32_t a0, uint32_t a1, uint32_t a2, uint32_t a3, uint32_t b0, uint32_t b1) {
    asm volatile(
        "mma.sync.aligned.m16n8k8.row.col.f32.tf32.tf32.f32 "
        "{%0,%1,%2,%3}, {%4,%5,%6,%7}, {%8,%9}, {%0,%1,%2,%3};"
        : "+f"(d[0]), "+f"(d[1]), "+f"(d[2]), "+f"(d[3])
        : "r"(a0), "r"(a1), "r"(a2), "r"(a3), "r"(b0), "r"(b1));
}
#define CP_COMMIT() asm volatile("cp.async.commit_group;" ::: "memory")
#define CP_WAIT1()  asm volatile("cp.async.wait_group 1;" ::: "memory")

__device__ __forceinline__ void cp16(float* s, const float* g) {
    asm volatile("cp.async.cg.shared.global [%0], [%1], 16;"
                 :: "r"(smem_u32(s)), "l"(g) : "memory");
}

// --- tile loaders (512 threads) ---
// normal K-major tile: ROWS x 32 floats, padded stride LDN
template<int ROWS>
__device__ __forceinline__ void load_n(const float* __restrict__ g, int ld, float* s, int tid) {
    #pragma unroll
    for (int i = 0; i < ROWS * 8 / NT; i++) {
        int idx = i * NT + tid, r = idx >> 3, c = (idx & 7) * 4;
        cp16(s + r * LDN + c, g + (size_t)r * ld + c);
    }
}
// transposed tile: 32 rows (k) x COLS, padded stride LDS
template<int COLS, int LDS>
__device__ __forceinline__ void load_t(const float* __restrict__ g, int ld, float* s, int tid) {
    const int CPR = COLS / 4;              // 16B chunks per row
    #pragma unroll
    for (int i = 0; i < (32 * CPR) / NT; i++) {
        int idx = i * NT + tid, r = idx / CPR, c = (idx % CPR) * 4;
        cp16(s + r * LDS + c, g + (size_t)r * ld + c);
    }
}

// --- one BK=32 chunk, CTA tile 128x256, warp tile 64x32 (wm in 0..1, wo in 0..7)
template<bool AT, bool CA, bool BT, bool CB, int LDA, int LDB>
__device__ __forceinline__ void compute_chunk(const float* __restrict__ As,
                                              const float* __restrict__ Bs,
                                              int wm, int wo, int lane, float* acc) {
    const int g = lane >> 2, t = lane & 3;
    #pragma unroll
    for (int ks = 0; ks < 4; ks++) {
        const int k0 = ks * 8;
        uint32_t af[4][4];
        #pragma unroll
        for (int mf = 0; mf < 4; mf++) {
            int r = wm * 64 + mf * 16 + g;
            float v0, v1, v2, v3;
            if (AT) {
                v0 = As[(k0 + t) * LDA + r];     v1 = As[(k0 + t) * LDA + r + 8];
                v2 = As[(k0 + t + 4) * LDA + r]; v3 = As[(k0 + t + 4) * LDA + r + 8];
            } else {
                const float* p0 = As + r * LDA + k0 + t;
                const float* p1 = As + (r + 8) * LDA + k0 + t;
                v0 = p0[0]; v1 = p1[0]; v2 = p0[4]; v3 = p1[4];
            }
            if (CA) { af[mf][0]=to_tf32(v0); af[mf][1]=to_tf32(v1); af[mf][2]=to_tf32(v2); af[mf][3]=to_tf32(v3); }
            else    { af[mf][0]=__float_as_uint(v0); af[mf][1]=__float_as_uint(v1);
                      af[mf][2]=__float_as_uint(v2); af[mf][3]=__float_as_uint(v3); }
        }
        uint32_t bf[4][2];
        #pragma unroll
        for (int nf = 0; nf < 4; nf++) {
            int r = wo * 32 + nf * 8 + g;
            float v0, v1;
            if (BT) { v0 = Bs[(k0 + t) * LDB + r]; v1 = Bs[(k0 + t + 4) * LDB + r]; }
            else    { const float* p = Bs + r * LDB + k0 + t; v0 = p[0]; v1 = p[4]; }
            if (CB) { bf[nf][0] = to_tf32(v0); bf[nf][1] = to_tf32(v1); }
            else    { bf[nf][0] = __float_as_uint(v0); bf[nf][1] = __float_as_uint(v1); }
        }
        #pragma unroll
        for (int mf = 0; mf < 4; mf++)
            #pragma unroll
            for (int nf = 0; nf < 4; nf++)
                mma_tf32(acc + (mf * 4 + nf) * 4, af[mf][0], af[mf][1], af[mf][2], af[mf][3],
                         bf[nf][0], bf[nf][1]);
    }
}

__device__ __forceinline__ void zero_acc(float* acc) {
    #pragma unroll
    for (int i = 0; i < 64; i++) acc[i] = 0.f;
}

// ---------------------------------------------------------------------------
// k1: hT[b,e,o,n] = sum_f W_e[f,o] * X[b,n,f] + b_adj[e,o]
//     CTA tile: M=128 (o), N=256 (n); 16 chunks (8 per e); A read transposed.
// ---------------------------------------------------------------------------
__global__ __launch_bounds__(NT) void k1_ht(
    const float* __restrict__ X, const float* __restrict__ W_adj,
    const float* __restrict__ b_adj)
{
    extern __shared__ float sm[];
    const int tid = threadIdx.x, lane = tid & 31, wid = tid >> 5;
    const int wm = wid & 1, wo = wid >> 1;
    const int o0 = (blockIdx.x & 1) * 128, n0 = (blockIdx.x >> 1) * 256;
    const int b = blockIdx.y;

    const float* Bm = X + ((size_t)b * NN + n0) * FIN;
    float acc[64];
    zero_acc(acc);

    const int C = 16;
    #define K1_A(c) (W_adj + (size_t)((c) >> 3) * FIN * FOUT + (size_t)(((c) & 7) * BK) * FOUT + o0)
    #define K1_B(c) (Bm + ((c) & 7) * BK)
    #define K1_LD(c, s)  do {                                              \
        load_t<128, LDT1>(K1_A(c), FOUT, sm + (s) * K1_STAGE, tid);        \
        load_n<256>(K1_B(c), FIN, sm + (s) * K1_STAGE + K1_AF, tid);       \
        CP_COMMIT(); } while (0)

    K1_LD(0, 0);
    K1_LD(1, 1);

    const int g = lane >> 2, t = lane & 3;
    for (int c = 0; c < C; c++) {
        CP_WAIT1();
        __syncthreads();
        if (c + 2 < C) K1_LD(c + 2, (c + 2) % NSTAGE); else CP_COMMIT();
        const float* st = sm + (c % NSTAGE) * K1_STAGE;
        compute_chunk<true, true, false, true, LDT1, LDN>(st, st + K1_AF, wm, wo, lane, acc);

        if ((c & 7) == 7) {
            int e = c >> 3;
            #pragma unroll
            for (int mf = 0; mf < 4; mf++) {
                int r0 = o0 + wm * 64 + mf * 16 + g;
                float bias0 = b_adj[e * FOUT + r0];
                float bias1 = b_adj[e * FOUT + r0 + 8];
                #pragma unroll
                for (int nf = 0; nf < 4; nf++) {
                    int cc = n0 + wo * 32 + nf * 8 + 2 * t;
                    float* a4 = acc + (mf * 4 + nf) * 4;
                    float* d0 = g_hT + (((size_t)(b * EE + e) * FOUT) + r0) * NN + cc;
                    float* d1 = g_hT + (((size_t)(b * EE + e) * FOUT) + r0 + 8) * NN + cc;
                    *(float2*)d0 = make_float2(round_tf32(a4[0] + bias0), round_tf32(a4[1] + bias0));
                    *(float2*)d1 = make_float2(round_tf32(a4[2] + bias1), round_tf32(a4[3] + bias1));
                }
            }
            zero_acc(acc);
        }
    }
}

// ---------------------------------------------------------------------------
// k2: out[b,m,o] = relu( sum_e adj[b,e,m,:] . hT[b,e,o,:]
//                      + sum_f X[b,m,f] * W2[f,o] + b2[o] )
//     CTA tile: M=128 (m), N=256 (o = full FOUT); 40 chained chunks.
// ---------------------------------------------------------------------------
__global__ __launch_bounds__(NT) void k2_main(
    const float* __restrict__ adj, const float* __restrict__ X,
    const float* __restrict__ W2, const float* __restrict__ b2,
    float* __restrict__ out)
{
    extern __shared__ float sm[];
    const int tid = threadIdx.x, lane = tid & 31, wid = tid >> 5;
    const int wm = wid & 1, wo = wid >> 1;
    const int m0 = blockIdx.x * 128;
    const int b = blockIdx.y;

    const float* adjb = adj + (size_t)b * EE * NN * NN + (size_t)m0 * NN;
    const float* hTb  = g_hT + (size_t)b * EE * FOUT * NN;
    const float* Xb   = X + ((size_t)b * NN + m0) * FIN;

    float acc[64];
    zero_acc(acc);

    const int C = 40;  // 16 (e=0) + 16 (e=1) + 8 (lin2)
    #define K2_LD(c, s) do {                                                      \
        float* sA = sm + (s) * K2_STAGE;                                          \
        float* sB = sA + K2_AF;                                                   \
        if ((c) < 32) {                                                           \
            int e_ = (c) >> 4, kc_ = (c) & 15;                                    \
            load_n<128>(adjb + (size_t)e_ * NN * NN + kc_ * BK, NN, sA, tid);     \
            load_n<256>(hTb + (size_t)e_ * FOUT * NN + kc_ * BK, NN, sB, tid);    \
        } else {                                                                  \
            int kc_ = (c) - 32;                                                   \
            load_n<128>(Xb + kc_ * BK, FIN, sA, tid);                             \
            load_t<256, LDT2>(W2 + (size_t)(kc_ * BK) * FOUT, FOUT, sB, tid);     \
        }                                                                         \
        CP_COMMIT(); } while (0)

    K2_LD(0, 0);
    K2_LD(1, 1);

    for (int c = 0; c < C; c++) {
        CP_WAIT1();
        __syncthreads();
        if (c + 2 < C) K2_LD(c + 2, (c + 2) % NSTAGE); else CP_COMMIT();
        const float* st = sm + (c % NSTAGE) * K2_STAGE;
        if (c < 32)
            compute_chunk<false, true, false, false, LDN, LDN>(st, st + K2_AF, wm, wo, lane, acc);
        else
            compute_chunk<false, true, true, true, LDN, LDT2>(st, st + K2_AF, wm, wo, lane, acc);
    }

    // epilogue: + b2[o], relu, store
    const int g = lane >> 2, t = lane & 3;
    #pragma unroll
    for (int mf = 0; mf < 4; mf++) {
        int r0 = m0 + wm * 64 + mf * 16 + g;
        #pragma unroll
        for (int nf = 0; nf < 4; nf++) {
            int cc = wo * 32 + nf * 8 + 2 * t;
            float bx = b2[cc], by = b2[cc + 1];
            float* a4 = acc + (mf * 4 + nf) * 4;
            float* d0 = out + ((size_t)b * NN + r0) * FOUT + cc;
            float* d1 = out + ((size_t)b * NN + r0 + 8) * FOUT + cc;
            *(float2*)d0 = make_float2(fmaxf(a4[0] + bx, 0.f), fmaxf(a4[1] + by, 0.f));
            *(float2*)d1 = make_float2(fmaxf(a4[2] + bx, 0.f), fmaxf(a4[3] + by, 0.f));
        }
    }
}

// ---------------------------------------------------------------------------
extern "C" void kernel_launch(void* const* d_in, const int* in_sizes, int n_in,
                              void* d_out, int out_size)
{
    const float* n_tensor   = (const float*)d_in[0];  // [32,512,256]
    const float* adj_tensor = (const float*)d_in[1];  // [32,2,512,512]
    const float* W_adj      = (const float*)d_in[2];  // [2,256,256]
    const float* b_adj      = (const float*)d_in[3];  // [2,256]
    const float* W2         = (const float*)d_in[4];  // [256,256]
    const float* b2         = (const float*)d_in[5];  // [256]
    float*       out        = (float*)d_out;          // [32,512,256]

    cudaFuncSetAttribute(k1_ht,   cudaFuncAttributeMaxDynamicSharedMemorySize, K1_SMEM);
    cudaFuncSetAttribute(k2_main, cudaFuncAttributeMaxDynamicSharedMemorySize, K2_SMEM);

    k1_ht<<<dim3(4, BATCH), NT, K1_SMEM>>>(n_tensor, W_adj, b_adj);
    k2_main<<<dim3(4, BATCH), NT, K2_SMEM>>>(adj_tensor, n_tensor, W2, b2, out);
}

// round 7
// speedup vs baseline: 1.6207x; 1.6207x over previous
#include <cuda_runtime.h>
#include <cuda_fp16.h>
#include <cstdint>

#define BATCH 32
#define NN    512
#define FIN   256
#define FOUT  256
#define EE    2

#define BK    32
#define LDF   40        // fp32 tile stride (floats)  -> LDS.64 conflict-free
#define LDH   40        // fp16 tile stride (halves)  -> LDS.32 conflict-free
#define NT    256

#define K1_ABYTES (128 * LDH * 2)                 // 10240
#define K1_STAGEB (K1_ABYTES + 256 * LDF * 4)     // 51200
#define K1_SMEMB  (3 * K1_STAGEB)                 // 153600
#define K2_ABYTES (128 * LDF * 4)                 // 20480
#define K2_STAGEB (K2_ABYTES + 256 * LDH * 2)     // 40960
#define K2_SMEMB  (3 * K2_STAGEB)                 // 122880

// scratch (no allocation allowed)
__device__ __half g_hTh[(size_t)BATCH * EE * FOUT * NN];  // [b][e][o][n]
__device__ __half g_WTh[3 * FIN * FOUT];                  // [z][o][f]; z=0,1 W_adj^T; z=2 W2^T

// ---------------------------------------------------------------- helpers ---
__device__ __forceinline__ uint32_t smem_u32(const void* p) {
    uint32_t a;
    asm("{ .reg .u64 t; cvta.to.shared.u64 t, %1; cvt.u32.u64 %0, t; }" : "=r"(a) : "l"(p));
    return a;
}
__device__ __forceinline__ uint32_t pack_h2(float lo, float hi) {
    uint32_t r;
    asm("cvt.rn.f16x2.f32 %0, %1, %2;" : "=r"(r) : "f"(hi), "f"(lo));
    return r;
}
__device__ __forceinline__ void mma16816(float* d, const uint32_t* a, uint32_t b0, uint32_t b1) {
    asm volatile(
        "mma.sync.aligned.m16n8k16.row.col.f32.f16.f16.f32 "
        "{%0,%1,%2,%3}, {%4,%5,%6,%7}, {%8,%9}, {%0,%1,%2,%3};"
        : "+f"(d[0]), "+f"(d[1]), "+f"(d[2]), "+f"(d[3])
        : "r"(a[0]), "r"(a[1]), "r"(a[2]), "r"(a[3]), "r"(b0), "r"(b1));
}
#define CP_COMMIT() asm volatile("cp.async.commit_group;" ::: "memory")
#define CP_WAIT1()  asm volatile("cp.async.wait_group 1;" ::: "memory")

__device__ __forceinline__ void cp16(void* s, const void* g) {
    asm volatile("cp.async.cg.shared.global [%0], [%1], 16;"
                 :: "r"(smem_u32(s)), "l"(g) : "memory");
}

// --- tile loaders (256 threads) ---
// fp32 K-major tile: ROWS x 32 floats, smem stride LDF
template<int ROWS>
__device__ __forceinline__ void load_f32t(const float* __restrict__ g, int ld, float* s, int tid) {
    #pragma unroll
    for (int i = 0; i < ROWS / 32; i++) {
        int idx = i * NT + tid, r = idx >> 3, c = (idx & 7) * 4;
        cp16(s + r * LDF + c, g + (size_t)r * ld + c);
    }
}
// fp16 K-major tile: ROWS x 32 halves, smem stride LDH
template<int ROWS>
__device__ __forceinline__ void load_f16t(const __half* __restrict__ g, int ld, __half* s, int tid) {
    #pragma unroll
    for (int i = 0; i < ROWS / 64; i++) {
        int idx = i * NT + tid, r = idx >> 2, c = (idx & 3) * 8;
        cp16(s + r * LDH + c, g + (size_t)r * ld + c);
    }
}

// --- one BK=32 chunk, CTA tile 128x256, warp tile 64x64 (wm 0..1, wo 0..3) ---
// AH/BH: operand is fp16 in smem (direct f16x2 LDS) vs fp32 (LDS.64 + cvt pack)
template<bool AH, bool BH>
__device__ __forceinline__ void compute_chunk16(const void* As, const void* Bs,
                                                int wm, int wo, int lane, float* acc) {
    const int g = lane >> 2, t = lane & 3;
    #pragma unroll
    for (int ks = 0; ks < 2; ks++) {
        const int k0 = ks * 16;
        uint32_t af[4][4];
        #pragma unroll
        for (int mf = 0; mf < 4; mf++) {
            int r = wm * 64 + mf * 16 + g;
            if (AH) {
                const __half* A = (const __half*)As;
                af[mf][0] = *(const uint32_t*)(A + r * LDH + k0 + 2 * t);
                af[mf][1] = *(const uint32_t*)(A + (r + 8) * LDH + k0 + 2 * t);
                af[mf][2] = *(const uint32_t*)(A + r * LDH + k0 + 8 + 2 * t);
                af[mf][3] = *(const uint32_t*)(A + (r + 8) * LDH + k0 + 8 + 2 * t);
            } else {
                const float* A = (const float*)As;
                float2 v0 = *(const float2*)(A + r * LDF + k0 + 2 * t);
                float2 v1 = *(const float2*)(A + (r + 8) * LDF + k0 + 2 * t);
                float2 v2 = *(const float2*)(A + r * LDF + k0 + 8 + 2 * t);
                float2 v3 = *(const float2*)(A + (r + 8) * LDF + k0 + 8 + 2 * t);
                af[mf][0] = pack_h2(v0.x, v0.y);
                af[mf][1] = pack_h2(v1.x, v1.y);
                af[mf][2] = pack_h2(v2.x, v2.y);
                af[mf][3] = pack_h2(v3.x, v3.y);
            }
        }
        uint32_t bf[8][2];
        #pragma unroll
        for (int nf = 0; nf < 8; nf++) {
            int n = wo * 64 + nf * 8 + g;
            if (BH) {
                const __half* B = (const __half*)Bs;
                bf[nf][0] = *(const uint32_t*)(B + n * LDH + k0 + 2 * t);
                bf[nf][1] = *(const uint32_t*)(B + n * LDH + k0 + 8 + 2 * t);
            } else {
                const float* B = (const float*)Bs;
                float2 v0 = *(const float2*)(B + n * LDF + k0 + 2 * t);
                float2 v1 = *(const float2*)(B + n * LDF + k0 + 8 + 2 * t);
                bf[nf][0] = pack_h2(v0.x, v0.y);
                bf[nf][1] = pack_h2(v1.x, v1.y);
            }
        }
        #pragma unroll
        for (int mf = 0; mf < 4; mf++)
            #pragma unroll
            for (int nf = 0; nf < 8; nf++)
                mma16816(acc + (mf * 8 + nf) * 4, af[mf], bf[nf][0], bf[nf][1]);
    }
}

__device__ __forceinline__ void zero_acc(float* acc) {
    #pragma unroll
    for (int i = 0; i < 128; i++) acc[i] = 0.f;
}

// ---------------------------------------------------------------------------
// k0: W transposes into g_WTh ([f][o] -> [o][f]) as fp16
// ---------------------------------------------------------------------------
__global__ void k0_transpose(const float* __restrict__ W_adj, const float* __restrict__ W2)
{
    __shared__ float t[32][33];
    int z = blockIdx.z;
    const float* src = (z < 2) ? (W_adj + (size_t)z * FIN * FOUT) : W2;
    int bo = blockIdx.x * 32, bf = blockIdx.y * 32;
    int tx = threadIdx.x, ty = threadIdx.y;
    #pragma unroll
    for (int j = 0; j < 32; j += 8) t[ty + j][tx] = src[(size_t)(bf + ty + j) * FOUT + bo + tx];
    __syncthreads();
    __half* dst = g_WTh + (size_t)z * FIN * FOUT;
    #pragma unroll
    for (int j = 0; j < 32; j += 8)
        dst[(size_t)(bo + ty + j) * FIN + bf + tx] = __float2half_rn(t[tx][ty + j]);
}

// ---------------------------------------------------------------------------
// k1: hTh[b,e,o,n] = fp16( sum_f WTh_e[o,f] * X[b,n,f] + b_adj[e,o] )
//     CTA tile: M=128 (o), N=256 (n); 16 chunks (8 per e)
// ---------------------------------------------------------------------------
__global__ __launch_bounds__(NT) void k1_ht(
    const float* __restrict__ X, const float* __restrict__ b_adj)
{
    extern __shared__ char smc[];
    const int tid = threadIdx.x, lane = tid & 31, wid = tid >> 5;
    const int wm = wid & 1, wo = wid >> 1;
    const int o0 = (blockIdx.x & 1) * 128, n0 = (blockIdx.x >> 1) * 256;
    const int b = blockIdx.y;

    const float* Bm = X + ((size_t)b * NN + n0) * FIN;
    float acc[128];
    zero_acc(acc);

    const int C = 16;
    #define K1_A(c) (g_WTh + (size_t)((c) >> 3) * FIN * FOUT + (size_t)o0 * FIN + ((c) & 7) * BK)
    #define K1_B(c) (Bm + ((c) & 7) * BK)
    #define K1_LD(c, s) do {                                                          \
        char* sb = smc + (s) * K1_STAGEB;                                             \
        load_f16t<128>(K1_A(c), FIN, (__half*)sb, tid);                               \
        load_f32t<256>(K1_B(c), FIN, (float*)(sb + K1_ABYTES), tid);                  \
        CP_COMMIT(); } while (0)

    K1_LD(0, 0);
    K1_LD(1, 1);

    const int g = lane >> 2, t = lane & 3;
    for (int c = 0; c < C; c++) {
        CP_WAIT1();
        __syncthreads();
        if (c + 2 < C) K1_LD(c + 2, (c + 2) % 3); else CP_COMMIT();
        char* sb = smc + (c % 3) * K1_STAGEB;
        compute_chunk16<true, false>(sb, sb + K1_ABYTES, wm, wo, lane, acc);

        if ((c & 7) == 7) {
            int e = c >> 3;
            #pragma unroll
            for (int mf = 0; mf < 4; mf++) {
                int r0 = o0 + wm * 64 + mf * 16 + g;
                float bias0 = b_adj[e * FOUT + r0];
                float bias1 = b_adj[e * FOUT + r0 + 8];
                #pragma unroll
                for (int nf = 0; nf < 8; nf++) {
                    int cc = n0 + wo * 64 + nf * 8 + 2 * t;
                    float* a4 = acc + (mf * 8 + nf) * 4;
                    __half2* d0 = (__half2*)(g_hTh + (((size_t)(b * EE + e) * FOUT) + r0) * NN + cc);
                    __half2* d1 = (__half2*)(g_hTh + (((size_t)(b * EE + e) * FOUT) + r0 + 8) * NN + cc);
                    *d0 = __floats2half2_rn(a4[0] + bias0, a4[1] + bias0);
                    *d1 = __floats2half2_rn(a4[2] + bias1, a4[3] + bias1);
                }
            }
            zero_acc(acc);
        }
    }
}

// ---------------------------------------------------------------------------
// k2: out[b,m,o] = relu( sum_e adj[b,e,m,:] . hTh[b,e,o,:]
//                      + sum_f X[b,m,f] * WTh2[o,f] + b2[o] )
//     CTA tile: M=128 (m), N=256 (o); 40 chained chunks
// ---------------------------------------------------------------------------
__global__ __launch_bounds__(NT) void k2_main(
    const float* __restrict__ adj, const float* __restrict__ X,
    const float* __restrict__ b2, float* __restrict__ out)
{
    extern __shared__ char smc[];
    const int tid = threadIdx.x, lane = tid & 31, wid = tid >> 5;
    const int wm = wid & 1, wo = wid >> 1;
    const int m0 = blockIdx.x * 128;
    const int b = blockIdx.y;

    const float*  adjb = adj + (size_t)b * EE * NN * NN + (size_t)m0 * NN;
    const __half* hTb  = g_hTh + (size_t)b * EE * FOUT * NN;
    const float*  Xb   = X + ((size_t)b * NN + m0) * FIN;
    const __half* W2T  = g_WTh + (size_t)2 * FIN * FOUT;

    float acc[128];
    zero_acc(acc);

    const int C = 40;  // 16 (e=0) + 16 (e=1) + 8 (lin2)
    #define K2_LD(c, s) do {                                                          \
        char* sb = smc + (s) * K2_STAGEB;                                             \
        float* sA = (float*)sb;                                                       \
        __half* sB = (__half*)(sb + K2_ABYTES);                                       \
        if ((c) < 32) {                                                               \
            int e_ = (c) >> 4, kc_ = (c) & 15;                                        \
            load_f32t<128>(adjb + (size_t)e_ * NN * NN + kc_ * BK, NN, sA, tid);      \
            load_f16t<256>(hTb + (size_t)e_ * FOUT * NN + kc_ * BK, NN, sB, tid);     \
        } else {                                                                      \
            int kc_ = (c) - 32;                                                       \
            load_f32t<128>(Xb + kc_ * BK, FIN, sA, tid);                              \
            load_f16t<256>(W2T + kc_ * BK, FIN, sB, tid);                             \
        }                                                                             \
        CP_COMMIT(); } while (0)

    K2_LD(0, 0);
    K2_LD(1, 1);

    for (int c = 0; c < C; c++) {
        CP_WAIT1();
        __syncthreads();
        if (c + 2 < C) K2_LD(c + 2, (c + 2) % 3); else CP_COMMIT();
        char* sb = smc + (c % 3) * K2_STAGEB;
        compute_chunk16<false, true>(sb, sb + K2_ABYTES, wm, wo, lane, acc);
    }

    // epilogue: + b2[o], relu, store fp32
    const int g = lane >> 2, t = lane & 3;
    #pragma unroll
    for (int mf = 0; mf < 4; mf++) {
        int r0 = m0 + wm * 64 + mf * 16 + g;
        #pragma unroll
        for (int nf = 0; nf < 8; nf++) {
            int cc = wo * 64 + nf * 8 + 2 * t;
            float bx = b2[cc], by = b2[cc + 1];
            float* a4 = acc + (mf * 8 + nf) * 4;
            float* d0 = out + ((size_t)b * NN + r0) * FOUT + cc;
            float* d1 = out + ((size_t)b * NN + r0 + 8) * FOUT + cc;
            *(float2*)d0 = make_float2(fmaxf(a4[0] + bx, 0.f), fmaxf(a4[1] + by, 0.f));
            *(float2*)d1 = make_float2(fmaxf(a4[2] + bx, 0.f), fmaxf(a4[3] + by, 0.f));
        }
    }
}

// ---------------------------------------------------------------------------
extern "C" void kernel_launch(void* const* d_in, const int* in_sizes, int n_in,
                              void* d_out, int out_size)
{
    const float* n_tensor   = (const float*)d_in[0];  // [32,512,256]
    const float* adj_tensor = (const float*)d_in[1];  // [32,2,512,512]
    const float* W_adj      = (const float*)d_in[2];  // [2,256,256]
    const float* b_adj      = (const float*)d_in[3];  // [2,256]
    const float* W2         = (const float*)d_in[4];  // [256,256]
    const float* b2         = (const float*)d_in[5];  // [256]
    float*       out        = (float*)d_out;          // [32,512,256]

    cudaFuncSetAttribute(k1_ht,   cudaFuncAttributeMaxDynamicSharedMemorySize, K1_SMEMB);
    cudaFuncSetAttribute(k2_main, cudaFuncAttributeMaxDynamicSharedMemorySize, K2_SMEMB);

    k0_transpose<<<dim3(8, 8, 3), dim3(32, 8)>>>(W_adj, W2);
    k1_ht<<<dim3(4, BATCH), NT, K1_SMEMB>>>(n_tensor, b_adj);
    k2_main<<<dim3(4, BATCH), NT, K2_SMEMB>>>(adj_tensor, n_tensor, b2, out);
}